// round 2
// baseline (speedup 1.0000x reference)
#include <cuda_runtime.h>
#include <cuda_bf16.h>
#include <math.h>

// Problem constants: queries/keys/values [B,N,L,H,E] = [4,4,1024,8,64] fp32.
// For fixed (b,n,h): row l starts at  bn*L*H*E + l*H*E + h*E, contiguous E=64 floats.

#define Bc 4
#define Nc 4
#define Lc 1024
#define Hc 8
#define Ec 64
#define ROWSTRIDE (Hc*Ec)   // 512 floats between consecutive l

#define LTILE 128           // query rows per block
#define STILE 64            // key rows per tile
#define PAD   68            // smem row pitch (floats): 68*4B = 272B, 16B-aligned, bank stride 4
#define NTHREADS 256

__device__ __forceinline__ float redmax16(float v) {
    v = fmaxf(v, __shfl_xor_sync(0xffffffffu, v, 8));
    v = fmaxf(v, __shfl_xor_sync(0xffffffffu, v, 4));
    v = fmaxf(v, __shfl_xor_sync(0xffffffffu, v, 2));
    v = fmaxf(v, __shfl_xor_sync(0xffffffffu, v, 1));
    return v;
}
__device__ __forceinline__ float redsum16(float v) {
    v += __shfl_xor_sync(0xffffffffu, v, 8);
    v += __shfl_xor_sync(0xffffffffu, v, 4);
    v += __shfl_xor_sync(0xffffffffu, v, 2);
    v += __shfl_xor_sync(0xffffffffu, v, 1);
    return v;
}

extern "C" __global__ void __launch_bounds__(NTHREADS, 2)
attn_fwd_kernel(const float* __restrict__ Q,
                const float* __restrict__ K,
                const float* __restrict__ V,
                float* __restrict__ O)
{
    extern __shared__ float smem[];
    float* sQ = smem;                       // [LTILE][PAD]
    float* sK = sQ + LTILE * PAD;           // [STILE][PAD]
    float* sV = sK + STILE * PAD;           // [STILE][PAD]
    float* sP = sV + STILE * PAD;           // [LTILE][PAD]

    const int tid = threadIdx.x;
    const int ty  = tid >> 4;               // 0..15  (row group)
    const int tx  = tid & 15;               // 0..15  (col group)

    const int qt  = blockIdx.x;             // 0..7
    const int bnh = blockIdx.y;             // 0..127
    const int h   = bnh & (Hc - 1);
    const int bn  = bnh >> 3;
    const size_t base = (size_t)bn * Lc * ROWSTRIDE + (size_t)h * Ec;
    const int q0 = qt * LTILE;

    // ---- load Q tile [128 x 64] into smem (float4, coalesced) ----
    {
        const int lr = tid >> 4;            // 0..15
        const int le = (tid & 15) << 2;     // 0,4,..,60
        #pragma unroll
        for (int it = 0; it < LTILE / 16; ++it) {
            int r = it * 16 + lr;
            float4 v = *(const float4*)(Q + base + (size_t)(q0 + r) * ROWSTRIDE + le);
            *(float4*)(&sQ[r * PAD + le]) = v;
        }
    }

    float m_i[8], l_i[8], acc[8][4];
    #pragma unroll
    for (int i = 0; i < 8; ++i) {
        m_i[i] = -INFINITY; l_i[i] = 0.f;
        #pragma unroll
        for (int j = 0; j < 4; ++j) acc[i][j] = 0.f;
    }

    const float scale = 0.125f;             // 1/sqrt(64)
    const int nkt = 2 * qt + 2;             // causal: key tiles 0 .. 2qt+1

    for (int kt = 0; kt < nkt; ++kt) {
        const int k0 = kt * STILE;

        __syncthreads();                    // prior GEMM2 reads of sK/sV/sP done
        // ---- load K,V tiles [64 x 64] ----
        {
            const int lr = tid >> 4;
            const int le = (tid & 15) << 2;
            #pragma unroll
            for (int it = 0; it < STILE / 16; ++it) {
                int r = it * 16 + lr;
                size_t g = base + (size_t)(k0 + r) * ROWSTRIDE + le;
                *(float4*)(&sK[r * PAD + le]) = *(const float4*)(K + g);
                *(float4*)(&sV[r * PAD + le]) = *(const float4*)(V + g);
            }
        }
        __syncthreads();

        // ---- GEMM1: S[r][c] = sum_e Q[r][e] * K[c][e] ----
        float s[8][4];
        #pragma unroll
        for (int i = 0; i < 8; ++i)
            #pragma unroll
            for (int j = 0; j < 4; ++j) s[i][j] = 0.f;

        #pragma unroll
        for (int e = 0; e < Ec; e += 4) {
            float4 kv[4];
            #pragma unroll
            for (int j = 0; j < 4; ++j)
                kv[j] = *(const float4*)(&sK[(tx + 16 * j) * PAD + e]);
            #pragma unroll
            for (int i = 0; i < 8; ++i) {
                float4 qv = *(const float4*)(&sQ[(ty + 16 * i) * PAD + e]);
                #pragma unroll
                for (int j = 0; j < 4; ++j) {
                    s[i][j] = fmaf(qv.x, kv[j].x, s[i][j]);
                    s[i][j] = fmaf(qv.y, kv[j].y, s[i][j]);
                    s[i][j] = fmaf(qv.z, kv[j].z, s[i][j]);
                    s[i][j] = fmaf(qv.w, kv[j].w, s[i][j]);
                }
            }
        }

        // ---- scale + causal mask (only tiles touching the diagonal) ----
        const bool need_mask = (k0 + STILE - 1 > q0);
        #pragma unroll
        for (int i = 0; i < 8; ++i) {
            int qg = q0 + ty + 16 * i;
            #pragma unroll
            for (int j = 0; j < 4; ++j) {
                float sv = s[i][j] * scale;
                if (need_mask && (k0 + tx + 16 * j) > qg) sv = -INFINITY;
                s[i][j] = sv;
            }
        }

        // ---- online softmax (row = 16 contiguous lanes) + write P ----
        #pragma unroll
        for (int i = 0; i < 8; ++i) {
            float mx = fmaxf(fmaxf(s[i][0], s[i][1]), fmaxf(s[i][2], s[i][3]));
            mx = redmax16(mx);
            float mnew = fmaxf(m_i[i], mx);
            // m_i=-inf & mnew finite -> corr=0; fully-masked tile row -> mnew=m_i, corr=1
            float corr = __expf(m_i[i] - mnew);
            float psum = 0.f;
            #pragma unroll
            for (int j = 0; j < 4; ++j) {
                float p = __expf(s[i][j] - mnew);   // exp(-inf)=0 for masked
                s[i][j] = p;
                psum += p;
            }
            psum = redsum16(psum);
            l_i[i] = l_i[i] * corr + psum;
            m_i[i] = mnew;
            #pragma unroll
            for (int j = 0; j < 4; ++j) {
                acc[i][j] *= corr;
                sP[(ty + 16 * i) * PAD + tx + 16 * j] = s[i][j];
            }
        }
        __syncthreads();                    // P visible to all

        // ---- GEMM2: acc[r][d] += sum_s P[r][s] * V[s][d] ----
        #pragma unroll
        for (int ss = 0; ss < STILE; ss += 4) {
            float vv[4][4];
            #pragma unroll
            for (int u = 0; u < 4; ++u)
                #pragma unroll
                for (int j = 0; j < 4; ++j)
                    vv[u][j] = sV[(ss + u) * PAD + tx + 16 * j];
            #pragma unroll
            for (int i = 0; i < 8; ++i) {
                float4 pv = *(const float4*)(&sP[(ty + 16 * i) * PAD + ss]);
                #pragma unroll
                for (int j = 0; j < 4; ++j) {
                    acc[i][j] = fmaf(pv.x, vv[0][j], acc[i][j]);
                    acc[i][j] = fmaf(pv.y, vv[1][j], acc[i][j]);
                    acc[i][j] = fmaf(pv.z, vv[2][j], acc[i][j]);
                    acc[i][j] = fmaf(pv.w, vv[3][j], acc[i][j]);
                }
            }
        }
    }

    // ---- epilogue: normalize and store ----
    #pragma unroll
    for (int i = 0; i < 8; ++i) {
        float inv = 1.f / l_i[i];
        size_t row = base + (size_t)(q0 + ty + 16 * i) * ROWSTRIDE;
        #pragma unroll
        for (int j = 0; j < 4; ++j)
            O[row + tx + 16 * j] = acc[i][j] * inv;
    }
}

extern "C" void kernel_launch(void* const* d_in, const int* in_sizes, int n_in,
                              void* d_out, int out_size)
{
    const float* Q = (const float*)d_in[0];
    const float* K = (const float*)d_in[1];
    const float* V = (const float*)d_in[2];
    float* O = (float*)d_out;

    const int smem_bytes = (LTILE + STILE + STILE + LTILE) * PAD * sizeof(float); // 104448
    cudaFuncSetAttribute(attn_fwd_kernel,
                         cudaFuncAttributeMaxDynamicSharedMemorySize, smem_bytes);

    dim3 grid(Lc / LTILE, Bc * Nc * Hc);    // (8, 128)
    attn_fwd_kernel<<<grid, NTHREADS, smem_bytes>>>(Q, K, V, O);
}

// round 4
// speedup vs baseline: 3.2429x; 3.2429x over previous
#include <cuda_runtime.h>
#include <math.h>
#include <stdint.h>

// [B,N,L,H,E] = [4,4,1024,8,64] fp32. For fixed (b,n,h): row l at bn*L*H*E + l*H*E + h*E,
// contiguous E=64 floats, stride H*E=512 floats between consecutive l.

#define Bc 4
#define Nc 4
#define Lc 1024
#define Hc 8
#define Ec 64
#define ROWSTRIDE (Hc*Ec)

#define LTILE 128
#define STILE 64
#define NTHREADS 256
#define PADA 68            // pitch (words) for sQ/sK/sP: bank = 4*row + col -> permutation
#define PADV 72            // pitch (words) for sV: bank = 8*(lane%4)+(lane>>2) -> permutation

#define SQ_W (LTILE*PADA)  // 8704
#define SK_W (STILE*PADA)  // 4352
#define SV_W (STILE*PADV)  // 4608
#define SP_W (LTILE*PADA)  // 8704
#define SMEM_WORDS (SQ_W + SK_W + SV_W + SP_W)   // 26368 words = 105472 B

static __device__ __forceinline__ uint32_t f2tf(float f) {
    uint32_t u; asm("cvt.rna.tf32.f32 %0, %1;" : "=r"(u) : "f"(f)); return u;
}

// D(16x8,f32) += A(16x8,tf32,row) * B(8x8,tf32,col)
static __device__ __forceinline__ void mma8(float* c, const uint32_t* a, const uint32_t* b) {
    asm volatile(
        "mma.sync.aligned.m16n8k8.row.col.f32.tf32.tf32.f32 "
        "{%0,%1,%2,%3}, {%4,%5,%6,%7}, {%8,%9}, {%0,%1,%2,%3};"
        : "+f"(c[0]), "+f"(c[1]), "+f"(c[2]), "+f"(c[3])
        : "r"(a[0]), "r"(a[1]), "r"(a[2]), "r"(a[3]), "r"(b[0]), "r"(b[1]));
}

extern "C" __global__ void __launch_bounds__(NTHREADS, 2)
attn_tc_kernel(const float* __restrict__ Q, const float* __restrict__ K,
               const float* __restrict__ V, float* __restrict__ O)
{
    extern __shared__ uint32_t smem[];
    uint32_t* sQ = smem;
    uint32_t* sK = sQ + SQ_W;
    uint32_t* sV = sK + SK_W;
    uint32_t* sP = sV + SV_W;

    const int tid  = threadIdx.x;
    const int w    = tid >> 5;          // warp 0..7, owns query rows [w*16, w*16+16)
    const int lane = tid & 31;
    const int g    = lane >> 2;         // groupID 0..7
    const int t    = lane & 3;          // threadID-in-group 0..3

    const int qt  = blockIdx.x;         // 0..7
    const int bnh = blockIdx.y;         // 0..127
    const int h   = bnh & (Hc - 1);
    const int bn  = bnh >> 3;
    const size_t base = (size_t)bn * Lc * ROWSTRIDE + (size_t)h * Ec;
    const int q0 = qt * LTILE;

    // ---- Q tile -> smem, pre-scaled by 1/sqrt(E), rounded to tf32 ----
    {
        const int lr = tid >> 4, le = (tid & 15) << 2;
        #pragma unroll
        for (int it = 0; it < LTILE / 16; ++it) {
            int r = it * 16 + lr;
            float4 v = *(const float4*)(Q + base + (size_t)(q0 + r) * ROWSTRIDE + le);
            uint4 u;
            u.x = f2tf(v.x * 0.125f); u.y = f2tf(v.y * 0.125f);
            u.z = f2tf(v.z * 0.125f); u.w = f2tf(v.w * 0.125f);
            *(uint4*)(&sQ[r * PADA + le]) = u;
        }
    }

    float o[8][4];
    #pragma unroll
    for (int nt = 0; nt < 8; ++nt) { o[nt][0]=0.f; o[nt][1]=0.f; o[nt][2]=0.f; o[nt][3]=0.f; }
    float m0 = -INFINITY, m1 = -INFINITY, l0 = 0.f, l1 = 0.f;

    const int rw  = w * 16;             // warp row offset within tile
    const int r0g = q0 + rw + g;        // global query row for fragment row-set 0 (row-set 1 = +8)
    const int nkt = 2 * qt + 2;         // causal: key tiles 0 .. 2qt+1

    for (int kt = 0; kt < nkt; ++kt) {
        const int k0 = kt * STILE;

        __syncthreads();                // previous GEMM2 done reading sK/sV
        {
            const int lr = tid >> 4, le = (tid & 15) << 2;
            #pragma unroll
            for (int it = 0; it < STILE / 16; ++it) {
                int r = it * 16 + lr;
                size_t ga = base + (size_t)(k0 + r) * ROWSTRIDE + le;
                float4 kv = *(const float4*)(K + ga);
                float4 vv = *(const float4*)(V + ga);
                uint4 uk, uv;
                uk.x = f2tf(kv.x); uk.y = f2tf(kv.y); uk.z = f2tf(kv.z); uk.w = f2tf(kv.w);
                uv.x = f2tf(vv.x); uv.y = f2tf(vv.y); uv.z = f2tf(vv.z); uv.w = f2tf(vv.w);
                *(uint4*)(&sK[r * PADA + le]) = uk;
                *(uint4*)(&sV[r * PADV + le]) = uv;
            }
        }
        __syncthreads();

        // Warp entirely above the diagonal for this key tile -> nothing to do.
        if (k0 > q0 + rw + 15) continue;

        // ---- GEMM1: S(16x64) = Q_w(16x64) * K^T, tensor cores ----
        float s[8][4];
        #pragma unroll
        for (int nt = 0; nt < 8; ++nt) { s[nt][0]=0.f; s[nt][1]=0.f; s[nt][2]=0.f; s[nt][3]=0.f; }

        #pragma unroll
        for (int kk = 0; kk < 8; ++kk) {
            uint32_t a[4];
            const uint32_t* qp = &sQ[(rw + g) * PADA + kk * 8 + t];
            a[0] = qp[0]; a[1] = qp[8 * PADA]; a[2] = qp[4]; a[3] = qp[8 * PADA + 4];
            #pragma unroll
            for (int nt = 0; nt < 8; ++nt) {
                uint32_t b[2];
                const uint32_t* kp = &sK[(nt * 8 + g) * PADA + kk * 8 + t];
                b[0] = kp[0]; b[1] = kp[4];
                mma8(s[nt], a, b);
            }
        }

        // ---- causal mask (S already scaled via Q) ----
        if (k0 + STILE - 1 > q0 + rw) {
            #pragma unroll
            for (int nt = 0; nt < 8; ++nt) {
                int c = k0 + nt * 8 + 2 * t;
                if (c     > r0g)     s[nt][0] = -INFINITY;
                if (c + 1 > r0g)     s[nt][1] = -INFINITY;
                if (c     > r0g + 8) s[nt][2] = -INFINITY;
                if (c + 1 > r0g + 8) s[nt][3] = -INFINITY;
            }
        }

        // ---- online softmax; each output row lives on 4 lanes (same g) ----
        float mx0 = -INFINITY, mx1 = -INFINITY;
        #pragma unroll
        for (int nt = 0; nt < 8; ++nt) {
            mx0 = fmaxf(mx0, fmaxf(s[nt][0], s[nt][1]));
            mx1 = fmaxf(mx1, fmaxf(s[nt][2], s[nt][3]));
        }
        mx0 = fmaxf(mx0, __shfl_xor_sync(0xffffffffu, mx0, 1));
        mx0 = fmaxf(mx0, __shfl_xor_sync(0xffffffffu, mx0, 2));
        mx1 = fmaxf(mx1, __shfl_xor_sync(0xffffffffu, mx1, 1));
        mx1 = fmaxf(mx1, __shfl_xor_sync(0xffffffffu, mx1, 2));

        float mn0 = fmaxf(m0, mx0), mn1 = fmaxf(m1, mx1);
        float cr0 = __expf(m0 - mn0), cr1 = __expf(m1 - mn1);

        float ps0 = 0.f, ps1 = 0.f;
        #pragma unroll
        for (int nt = 0; nt < 8; ++nt) {
            s[nt][0] = __expf(s[nt][0] - mn0);
            s[nt][1] = __expf(s[nt][1] - mn0);
            s[nt][2] = __expf(s[nt][2] - mn1);
            s[nt][3] = __expf(s[nt][3] - mn1);
            ps0 += s[nt][0] + s[nt][1];
            ps1 += s[nt][2] + s[nt][3];
        }
        ps0 += __shfl_xor_sync(0xffffffffu, ps0, 1);
        ps0 += __shfl_xor_sync(0xffffffffu, ps0, 2);
        ps1 += __shfl_xor_sync(0xffffffffu, ps1, 1);
        ps1 += __shfl_xor_sync(0xffffffffu, ps1, 2);

        l0 = l0 * cr0 + ps0;  l1 = l1 * cr1 + ps1;
        m0 = mn0;             m1 = mn1;

        // ---- rescale O accumulators; stash P (tf32) in warp-private smem stripe ----
        #pragma unroll
        for (int nt = 0; nt < 8; ++nt) {
            o[nt][0] *= cr0; o[nt][1] *= cr0; o[nt][2] *= cr1; o[nt][3] *= cr1;
            uint2 p01; p01.x = f2tf(s[nt][0]); p01.y = f2tf(s[nt][1]);
            uint2 p23; p23.x = f2tf(s[nt][2]); p23.y = f2tf(s[nt][3]);
            *(uint2*)(&sP[(rw + g)     * PADA + nt * 8 + 2 * t]) = p01;
            *(uint2*)(&sP[(rw + g + 8) * PADA + nt * 8 + 2 * t]) = p23;
        }
        __syncwarp();   // P is only read by this warp

        // ---- GEMM2: O(16x64) += P(16x64) * V(64x64), tensor cores ----
        #pragma unroll
        for (int ks = 0; ks < 8; ++ks) {
            uint32_t a[4];
            const uint32_t* pp = &sP[(rw + g) * PADA + ks * 8 + t];
            a[0] = pp[0]; a[1] = pp[8 * PADA]; a[2] = pp[4]; a[3] = pp[8 * PADA + 4];
            #pragma unroll
            for (int nt = 0; nt < 8; ++nt) {
                uint32_t b[2];
                const uint32_t* vp = &sV[(ks * 8 + t) * PADV + nt * 8 + g];
                b[0] = vp[0]; b[1] = vp[4 * PADV];
                mma8(o[nt], a, b);
            }
        }
    }

    // ---- epilogue: normalize, store ----
    const float inv0 = 1.f / l0, inv1 = 1.f / l1;
    const size_t ro0 = base + (size_t)r0g * ROWSTRIDE;
    const size_t ro1 = ro0 + (size_t)8 * ROWSTRIDE;
    #pragma unroll
    for (int nt = 0; nt < 8; ++nt) {
        float2 v0; v0.x = o[nt][0] * inv0; v0.y = o[nt][1] * inv0;
        float2 v1; v1.x = o[nt][2] * inv1; v1.y = o[nt][3] * inv1;
        *(float2*)(O + ro0 + nt * 8 + 2 * t) = v0;
        *(float2*)(O + ro1 + nt * 8 + 2 * t) = v1;
    }
}

extern "C" void kernel_launch(void* const* d_in, const int* in_sizes, int n_in,
                              void* d_out, int out_size)
{
    const float* Q = (const float*)d_in[0];
    const float* K = (const float*)d_in[1];
    const float* V = (const float*)d_in[2];
    float* O = (float*)d_out;

    const int smem_bytes = SMEM_WORDS * (int)sizeof(uint32_t);   // 105472
    cudaFuncSetAttribute(attn_tc_kernel,
                         cudaFuncAttributeMaxDynamicSharedMemorySize, smem_bytes);

    dim3 grid(Lc / LTILE, Bc * Nc * Hc);    // (8, 128)
    attn_tc_kernel<<<grid, NTHREADS, smem_bytes>>>(Q, K, V, O);
}